// round 5
// baseline (speedup 1.0000x reference)
#include <cuda_runtime.h>
#include <cstdint>

#define N_LEVELS 16
#define TABLE_SIZE (1u << 19)
#define TMASK (TABLE_SIZE - 1u)
#define P1 2654435761u
#define P2 805459861u
#define BLOCK 128

using ull = unsigned long long;

__device__ __forceinline__ ull pack2(float lo, float hi) {
    ull r; asm("mov.b64 %0, {%1, %2};" : "=l"(r) : "f"(lo), "f"(hi)); return r;
}
__device__ __forceinline__ void unpack2(ull v, float& lo, float& hi) {
    asm("mov.b64 {%0, %1}, %2;" : "=f"(lo), "=f"(hi) : "l"(v));
}
__device__ __forceinline__ ull fma2(ull a, ull b, ull c) {
    ull d; asm("fma.rn.f32x2 %0, %1, %2, %3;" : "=l"(d) : "l"(a), "l"(b), "l"(c)); return d;
}

// Predicated gather: lanes with p==0 issue NO memory transaction (no BSSY,
// no L1 wavefronts) and keep the fallback value.
__device__ __forceinline__ float2 ldg_pred(const float2* ptr, unsigned p, float2 fb) {
    asm volatile("{\n\t"
                 ".reg .pred q;\n\t"
                 "setp.ne.u32 q, %3, 0;\n\t"
                 "@q ld.global.nc.v2.f32 {%0, %1}, [%2];\n\t"
                 "}"
                 : "+f"(fb.x), "+f"(fb.y) : "l"(ptr), "r"(p));
    return fb;
}

__global__ __launch_bounds__(BLOCK, 4)
void hashgrid_mlp_kernel(const float* __restrict__ x,
                         const float* __restrict__ tables,
                         const float* __restrict__ resolutions,
                         const float* __restrict__ W1, const float* __restrict__ b1,
                         const float* __restrict__ W2, const float* __restrict__ b2,
                         const float* __restrict__ W3, const float* __restrict__ b3,
                         float* __restrict__ out, int n)
{
    __shared__ __align__(16) float sW1[32 * 64];
    __shared__ __align__(16) float sW2[64 * 64];
    __shared__ __align__(16) float sB1[64];
    __shared__ __align__(16) float sB2[64];
    __shared__ __align__(16) float sW3[64];
    __shared__ float sRes[16];
    __shared__ float sB3;

    const int tid = threadIdx.x;
    for (int i = tid; i < 32 * 64; i += BLOCK) sW1[i] = W1[i];
    for (int i = tid; i < 64 * 64; i += BLOCK) sW2[i] = W2[i];
    if (tid < 64) { sB1[tid] = b1[tid]; sB2[tid] = b2[tid]; sW3[tid] = W3[tid]; }
    if (tid < 16) sRes[tid] = resolutions[tid];
    if (tid == 0) sB3 = b3[0];
    __syncthreads();

    const int p = blockIdx.x * BLOCK + tid;
    if (p >= n) return;

    const float x0 = x[3 * p + 0] * 0.5f + 0.5f;
    const float x1 = x[3 * p + 1] * 0.5f + 0.5f;
    const float x2 = x[3 * p + 2] * 0.5f + 0.5f;

    float a[2 * N_LEVELS];

    #pragma unroll
    for (int L = 0; L < N_LEVELS; L++) {
        const float r = sRes[L];
        const float px = x0 * r, py = x1 * r, pz = x2 * r;
        const float fx = floorf(px), fy = floorf(py), fz = floorf(pz);
        const float wx = px - fx, wy = py - fy, wz = pz - fz;
        const unsigned cx = (unsigned)fx, cy = (unsigned)fy, cz = (unsigned)fz;

        const unsigned hx0 = cx,        hx1 = cx + 1u;
        const unsigned hy0 = cy * P1,   hy1 = (cy + 1u) * P1;
        const unsigned hz0 = cz * P2,   hz1 = (cz + 1u) * P2;
        // cx even  =>  idx1 == idx0 ^ 1  =>  both x-corners live in one aligned float4
        const unsigned oddx = cx & 1u;

        const float2* __restrict__ tab =
            reinterpret_cast<const float2*>(tables) + (size_t)L * TABLE_SIZE;

        const float ox = 1.0f - wx, oy = 1.0f - wy, oz = 1.0f - wz;

        float ax = 0.0f, ay = 0.0f;
        // corner index c: bit0 = x, bit1 = y, bit2 = z; accumulate x0-corner then
        // x1-corner per yz => identical summation order to c = 0..7 => bit-exact.
        #pragma unroll
        for (int yz = 0; yz < 4; yz++) {
            const unsigned hr = ((yz & 1) ? hy1 : hy0) ^ ((yz & 2) ? hz1 : hz0);
            const float wyz = ((yz & 1) ? wy : oy) * ((yz & 2) ? wz : oz);

            const unsigned idx0 = (hx0 ^ hr) & TMASK;
            const unsigned idx1 = (hx1 ^ hr) & TMASK;

            // one aligned 16B load covering table entries (idx0 & ~1) and (idx0 | 1)
            const float4 q = __ldg(reinterpret_cast<const float4*>(tab + (idx0 & ~1u)));
            const bool low = (idx0 & 1u) == 0u;          // entry idx0 is q.xy?
            const float2 tA    = low ? make_float2(q.x, q.y) : make_float2(q.z, q.w);
            const float2 other = low ? make_float2(q.z, q.w) : make_float2(q.x, q.y);
            // even cx: x1-corner is the other half of q; odd cx: predicated gather
            const float2 tB = ldg_pred(tab + idx1, oddx, other);

            const float wA = ox * wyz;
            const float wB = wx * wyz;
            ax = fmaf(wA, tA.x, ax);
            ay = fmaf(wA, tA.y, ay);
            ax = fmaf(wB, tB.x, ax);
            ay = fmaf(wB, tB.y, ay);
        }
        a[2 * L + 0] = ax;
        a[2 * L + 1] = ay;
    }

    // ---- layer 1: [32] -> [64] packed as 32 f32x2 pairs over j ----
    ull h1p[32];
    #pragma unroll
    for (int j = 0; j < 32; j++)
        h1p[j] = *reinterpret_cast<const ull*>(&sB1[2 * j]);

    #pragma unroll
    for (int i = 0; i < 32; i++) {
        const ull ap = pack2(a[i], a[i]);
        const ull* wrow = reinterpret_cast<const ull*>(&sW1[i * 64]);
        #pragma unroll
        for (int j = 0; j < 32; j += 2) {
            const ulonglong2 w = *reinterpret_cast<const ulonglong2*>(&wrow[j]);
            h1p[j + 0] = fma2(ap, w.x, h1p[j + 0]);
            h1p[j + 1] = fma2(ap, w.y, h1p[j + 1]);
        }
    }

    // ---- layer 2: [64] -> [64] (packed over j, two halves), fused layer 3 ----
    float r3 = sB3;
    #pragma unroll
    for (int half = 0; half < 2; half++) {
        const int cb = 32 * half;
        ull acc[16];
        #pragma unroll
        for (int jj = 0; jj < 16; jj++)
            acc[jj] = *reinterpret_cast<const ull*>(&sB2[cb + 2 * jj]);

        #pragma unroll
        for (int i2 = 0; i2 < 32; i2++) {
            float lo, hi;
            unpack2(h1p[i2], lo, hi);
            lo = fmaxf(lo, 0.0f);
            hi = fmaxf(hi, 0.0f);
            const ull plo = pack2(lo, lo);
            const ull phi = pack2(hi, hi);
            const ull* w0 = reinterpret_cast<const ull*>(&sW2[(2 * i2 + 0) * 64 + cb]);
            const ull* w1 = reinterpret_cast<const ull*>(&sW2[(2 * i2 + 1) * 64 + cb]);
            #pragma unroll
            for (int jj = 0; jj < 16; jj += 2) {
                const ulonglong2 wa = *reinterpret_cast<const ulonglong2*>(&w0[jj]);
                acc[jj + 0] = fma2(plo, wa.x, acc[jj + 0]);
                acc[jj + 1] = fma2(plo, wa.y, acc[jj + 1]);
            }
            #pragma unroll
            for (int jj = 0; jj < 16; jj += 2) {
                const ulonglong2 wb = *reinterpret_cast<const ulonglong2*>(&w1[jj]);
                acc[jj + 0] = fma2(phi, wb.x, acc[jj + 0]);
                acc[jj + 1] = fma2(phi, wb.y, acc[jj + 1]);
            }
        }
        #pragma unroll
        for (int jj = 0; jj < 16; jj++) {
            float a0, a1;
            unpack2(acc[jj], a0, a1);
            r3 = fmaf(fmaxf(a0, 0.0f), sW3[cb + 2 * jj + 0], r3);
            r3 = fmaf(fmaxf(a1, 0.0f), sW3[cb + 2 * jj + 1], r3);
        }
    }

    out[p] = r3;
}

extern "C" void kernel_launch(void* const* d_in, const int* in_sizes, int n_in,
                              void* d_out, int out_size)
{
    const float* x    = (const float*)d_in[0];
    const float* tabs = (const float*)d_in[1];
    const float* res  = (const float*)d_in[2];
    const float* W1   = (const float*)d_in[3];
    const float* b1   = (const float*)d_in[4];
    const float* W2   = (const float*)d_in[5];
    const float* b2   = (const float*)d_in[6];
    const float* W3   = (const float*)d_in[7];
    const float* b3   = (const float*)d_in[8];
    float* out = (float*)d_out;

    const int n = in_sizes[0] / 3;
    const int grid = (n + BLOCK - 1) / BLOCK;
    hashgrid_mlp_kernel<<<grid, BLOCK>>>(x, tabs, res, W1, b1, W2, b2, W3, b3, out, n);
}

// round 6
// speedup vs baseline: 1.1450x; 1.1450x over previous
#include <cuda_runtime.h>
#include <cstdint>

#define N_LEVELS 16
#define TABLE_SIZE (1u << 19)
#define TMASK (TABLE_SIZE - 1u)
#define P1 2654435761u
#define P2 805459861u
#define BLOCK 128
#define MAXN 2000000
#define GBITS 5
#define GRES (1 << GBITS)            // 32 cells per dim
#define NCELLS (GRES * GRES * GRES)  // 32768

using ull = unsigned long long;

__device__ __forceinline__ ull pack2(float lo, float hi) {
    ull r; asm("mov.b64 %0, {%1, %2};" : "=l"(r) : "f"(lo), "f"(hi)); return r;
}
__device__ __forceinline__ void unpack2(ull v, float& lo, float& hi) {
    asm("mov.b64 {%0, %1}, %2;" : "=f"(lo), "=f"(hi) : "l"(v));
}
__device__ __forceinline__ ull fma2(ull a, ull b, ull c) {
    ull d; asm("fma.rn.f32x2 %0, %1, %2, %3;" : "=l"(d) : "l"(a), "l"(b), "l"(c)); return d;
}

// ---- static scratch (no allocation) ----
__device__ int    d_hist[NCELLS];
__device__ int    d_offs[NCELLS];
__device__ float4 d_xs[MAXN];   // bucket-sorted: (x01, y01, z01, bits(orig_idx))

__device__ __forceinline__ int cell_of(float x0, float x1, float x2) {
    int cx = min(GRES - 1, (int)(x0 * (float)GRES));
    int cy = min(GRES - 1, (int)(x1 * (float)GRES));
    int cz = min(GRES - 1, (int)(x2 * (float)GRES));
    return (cx << (2 * GBITS)) | (cy << GBITS) | cz;
}

__global__ void k_zero() {
    int i = blockIdx.x * blockDim.x + threadIdx.x;
    if (i < NCELLS) d_hist[i] = 0;
}

__global__ void k_hist(const float* __restrict__ x, int n) {
    int i = blockIdx.x * blockDim.x + threadIdx.x;
    if (i >= n) return;
    float x0 = x[3 * i + 0] * 0.5f + 0.5f;
    float x1 = x[3 * i + 1] * 0.5f + 0.5f;
    float x2 = x[3 * i + 2] * 0.5f + 0.5f;
    atomicAdd(&d_hist[cell_of(x0, x1, x2)], 1);
}

// exclusive scan of d_hist (32768) -> d_offs; one block of 1024, 32 per thread
__global__ void k_scan() {
    __shared__ int sc[1024];
    const int t = threadIdx.x;
    const int base = t * 32;
    int local[32];
    int s = 0;
    #pragma unroll
    for (int k = 0; k < 32; k++) { local[k] = s; s += d_hist[base + k]; }
    sc[t] = s;
    __syncthreads();
    // Hillis-Steele inclusive scan over thread sums
    #pragma unroll
    for (int d = 1; d < 1024; d <<= 1) {
        int v = (t >= d) ? sc[t - d] : 0;
        __syncthreads();
        sc[t] += v;
        __syncthreads();
    }
    const int excl = sc[t] - s;
    #pragma unroll
    for (int k = 0; k < 32; k++) d_offs[base + k] = excl + local[k];
}

__global__ void k_scatter(const float* __restrict__ x, int n) {
    int i = blockIdx.x * blockDim.x + threadIdx.x;
    if (i >= n) return;
    float x0 = x[3 * i + 0] * 0.5f + 0.5f;
    float x1 = x[3 * i + 1] * 0.5f + 0.5f;
    float x2 = x[3 * i + 2] * 0.5f + 0.5f;
    int pos = atomicAdd(&d_offs[cell_of(x0, x1, x2)], 1);
    d_xs[pos] = make_float4(x0, x1, x2, __int_as_float(i));
}

__global__ __launch_bounds__(BLOCK, 4)
void hashgrid_mlp_kernel(const float* __restrict__ tables,
                         const float* __restrict__ resolutions,
                         const float* __restrict__ W1, const float* __restrict__ b1,
                         const float* __restrict__ W2, const float* __restrict__ b2,
                         const float* __restrict__ W3, const float* __restrict__ b3,
                         float* __restrict__ out, int n)
{
    __shared__ __align__(16) float sW1[32 * 64];
    __shared__ __align__(16) float sW2[64 * 64];
    __shared__ __align__(16) float sB1[64];
    __shared__ __align__(16) float sB2[64];
    __shared__ __align__(16) float sW3[64];
    __shared__ float sRes[16];
    __shared__ float sB3;

    const int tid = threadIdx.x;
    for (int i = tid; i < 32 * 64; i += BLOCK) sW1[i] = W1[i];
    for (int i = tid; i < 64 * 64; i += BLOCK) sW2[i] = W2[i];
    if (tid < 64) { sB1[tid] = b1[tid]; sB2[tid] = b2[tid]; sW3[tid] = W3[tid]; }
    if (tid < 16) sRes[tid] = resolutions[tid];
    if (tid == 0) sB3 = b3[0];
    __syncthreads();

    const int p = blockIdx.x * BLOCK + tid;
    if (p >= n) return;

    const float4 xi = d_xs[p];            // coalesced; bucket-sorted point
    const float x0 = xi.x, x1 = xi.y, x2 = xi.z;
    const int oidx = __float_as_int(xi.w);

    float a[2 * N_LEVELS];

    #pragma unroll
    for (int L = 0; L < N_LEVELS; L++) {
        const float r = sRes[L];
        const float px = x0 * r, py = x1 * r, pz = x2 * r;
        const float fx = floorf(px), fy = floorf(py), fz = floorf(pz);
        const float wx = px - fx, wy = py - fy, wz = pz - fz;
        const unsigned cx = (unsigned)fx, cy = (unsigned)fy, cz = (unsigned)fz;

        const unsigned hx0 = cx,        hx1 = cx + 1u;
        const unsigned hy0 = cy * P1,   hy1 = (cy + 1u) * P1;
        const unsigned hz0 = cz * P2,   hz1 = (cz + 1u) * P2;

        const float2* __restrict__ tab =
            reinterpret_cast<const float2*>(tables) + (size_t)L * TABLE_SIZE;

        const float ox = 1.0f - wx, oy = 1.0f - wy, oz = 1.0f - wz;

        float ax = 0.0f, ay = 0.0f;
        #pragma unroll
        for (int c = 0; c < 8; c++) {
            const unsigned h = ((c & 1) ? hx1 : hx0)
                             ^ ((c & 2) ? hy1 : hy0)
                             ^ ((c & 4) ? hz1 : hz0);
            const unsigned idx = h & TMASK;
            const float2 t = __ldg(&tab[idx]);
            const float wc = ((c & 1) ? wx : ox)
                           * ((c & 2) ? wy : oy)
                           * ((c & 4) ? wz : oz);
            ax = fmaf(wc, t.x, ax);
            ay = fmaf(wc, t.y, ay);
        }
        a[2 * L + 0] = ax;
        a[2 * L + 1] = ay;
    }

    // ---- layer 1: [32] -> [64] packed as 32 f32x2 pairs over j ----
    ull h1p[32];
    #pragma unroll
    for (int j = 0; j < 32; j++)
        h1p[j] = *reinterpret_cast<const ull*>(&sB1[2 * j]);

    #pragma unroll
    for (int i = 0; i < 32; i++) {
        const ull ap = pack2(a[i], a[i]);
        const ull* wrow = reinterpret_cast<const ull*>(&sW1[i * 64]);
        #pragma unroll
        for (int j = 0; j < 32; j += 2) {
            const ulonglong2 w = *reinterpret_cast<const ulonglong2*>(&wrow[j]);
            h1p[j + 0] = fma2(ap, w.x, h1p[j + 0]);
            h1p[j + 1] = fma2(ap, w.y, h1p[j + 1]);
        }
    }

    // ---- layer 2: [64] -> [64] (packed over j, two halves), fused layer 3 ----
    float r3 = sB3;
    #pragma unroll
    for (int half = 0; half < 2; half++) {
        const int cb = 32 * half;
        ull acc[16];
        #pragma unroll
        for (int jj = 0; jj < 16; jj++)
            acc[jj] = *reinterpret_cast<const ull*>(&sB2[cb + 2 * jj]);

        #pragma unroll
        for (int i2 = 0; i2 < 32; i2++) {
            float lo, hi;
            unpack2(h1p[i2], lo, hi);
            lo = fmaxf(lo, 0.0f);
            hi = fmaxf(hi, 0.0f);
            const ull plo = pack2(lo, lo);
            const ull phi = pack2(hi, hi);
            const ull* w0 = reinterpret_cast<const ull*>(&sW2[(2 * i2 + 0) * 64 + cb]);
            const ull* w1 = reinterpret_cast<const ull*>(&sW2[(2 * i2 + 1) * 64 + cb]);
            #pragma unroll
            for (int jj = 0; jj < 16; jj += 2) {
                const ulonglong2 wa = *reinterpret_cast<const ulonglong2*>(&w0[jj]);
                acc[jj + 0] = fma2(plo, wa.x, acc[jj + 0]);
                acc[jj + 1] = fma2(plo, wa.y, acc[jj + 1]);
            }
            #pragma unroll
            for (int jj = 0; jj < 16; jj += 2) {
                const ulonglong2 wb = *reinterpret_cast<const ulonglong2*>(&w1[jj]);
                acc[jj + 0] = fma2(phi, wb.x, acc[jj + 0]);
                acc[jj + 1] = fma2(phi, wb.y, acc[jj + 1]);
            }
        }
        #pragma unroll
        for (int jj = 0; jj < 16; jj++) {
            float a0, a1;
            unpack2(acc[jj], a0, a1);
            r3 = fmaf(fmaxf(a0, 0.0f), sW3[cb + 2 * jj + 0], r3);
            r3 = fmaf(fmaxf(a1, 0.0f), sW3[cb + 2 * jj + 1], r3);
        }
    }

    out[oidx] = r3;
}

extern "C" void kernel_launch(void* const* d_in, const int* in_sizes, int n_in,
                              void* d_out, int out_size)
{
    const float* x    = (const float*)d_in[0];
    const float* tabs = (const float*)d_in[1];
    const float* res  = (const float*)d_in[2];
    const float* W1   = (const float*)d_in[3];
    const float* b1   = (const float*)d_in[4];
    const float* W2   = (const float*)d_in[5];
    const float* b2   = (const float*)d_in[6];
    const float* W3   = (const float*)d_in[7];
    const float* b3   = (const float*)d_in[8];
    float* out = (float*)d_out;

    const int n = in_sizes[0] / 3;

    k_zero<<<(NCELLS + 1023) / 1024, 1024>>>();
    k_hist<<<(n + 255) / 256, 256>>>(x, n);
    k_scan<<<1, 1024>>>();
    k_scatter<<<(n + 255) / 256, 256>>>(x, n);

    const int grid = (n + BLOCK - 1) / BLOCK;
    hashgrid_mlp_kernel<<<grid, BLOCK>>>(tabs, res, W1, b1, W2, b2, W3, b3, out, n);
}